// round 2
// baseline (speedup 1.0000x reference)
#include <cuda_runtime.h>

#define NB 524288
#define T_OBS 8
#define T_PRE 12
#define HH 8
#define EE 16

typedef unsigned long long ull;

// Duplicated (w,w) packed weights, pre-scaled by -log2e (gate g: -2*log2e)
struct __align__(16) Wpack {
    float2 W[2][8][8][4];   // [phase][j][k][gate]
    float2 A[2][8][2][4];   // [phase][j][m][gate]   (A = W_ih @ W_in, folded)
    float2 Bz[2][8][4];     // [phase][j][gate]      (b_ih + b_hh + W_ih@b_in, folded)
};
__device__ Wpack gPack;

// ---------------- prep: fold embedding into gate weights, scale, duplicate ----------------
__global__ void prep_kernel(
    const float* __restrict__ W_in, const float* __restrict__ b_in,
    const float* __restrict__ Wih_o, const float* __restrict__ Whh_o,
    const float* __restrict__ bih_o, const float* __restrict__ bhh_o,
    const float* __restrict__ Wih_p, const float* __restrict__ Whh_p,
    const float* __restrict__ bih_p, const float* __restrict__ bhh_p)
{
    int t = threadIdx.x;
    if (t >= 64) return;
    int ph = t >> 5, r = t & 31;
    const float* Wih = ph ? Wih_p : Wih_o;
    const float* Whh = ph ? Whh_p : Whh_o;
    const float* bih = ph ? bih_p : bih_o;
    const float* bhh = ph ? bhh_p : bhh_o;
    int g = r >> 3, j = r & 7;                       // rows: i(0-7) f(8-15) g(16-23) o(24-31)
    const float L2E = 1.4426950408889634f;
    float sc = (g == 2) ? (-2.0f * L2E) : (-L2E);    // fold sigmoid/tanh arg scaling into weights
    float a0 = 0.f, a1 = 0.f, bb = bih[r] + bhh[r];
    for (int e = 0; e < EE; e++) {
        float w = Wih[r * EE + e];
        a0 += w * W_in[e * 2 + 0];
        a1 += w * W_in[e * 2 + 1];
        bb += w * b_in[e];
    }
    a0 *= sc; a1 *= sc; bb *= sc;
    gPack.A[ph][j][0][g] = make_float2(a0, a0);
    gPack.A[ph][j][1][g] = make_float2(a1, a1);
    gPack.Bz[ph][j][g]   = make_float2(bb, bb);
    for (int k = 0; k < HH; k++) {
        float w = Whh[r * HH + k] * sc;
        gPack.W[ph][j][k][g] = make_float2(w, w);
    }
}

// ---------------- packed f32x2 helpers ----------------
__device__ __forceinline__ ull fma2(ull a, ull b, ull c) {
    ull d; asm("fma.rn.f32x2 %0, %1, %2, %3;" : "=l"(d) : "l"(a), "l"(b), "l"(c)); return d;
}
__device__ __forceinline__ ull mul2(ull a, ull b) {
    ull d; asm("mul.rn.f32x2 %0, %1, %2;" : "=l"(d) : "l"(a), "l"(b)); return d;
}
__device__ __forceinline__ ull add2(ull a, ull b) {
    ull d; asm("add.rn.f32x2 %0, %1, %2;" : "=l"(d) : "l"(a), "l"(b)); return d;
}
__device__ __forceinline__ ull pk(float lo, float hi) {
    ull d; asm("mov.b64 %0, {%1, %2};" : "=l"(d) : "f"(lo), "f"(hi)); return d;
}
__device__ __forceinline__ ull ex2_2(ull a) {   // elementwise 2^x on packed pair
    float lo, hi; asm("mov.b64 {%0, %1}, %2;" : "=f"(lo), "=f"(hi) : "l"(a));
    float el, eh;
    asm("ex2.approx.f32 %0, %1;" : "=f"(el) : "f"(lo));
    asm("ex2.approx.f32 %0, %1;" : "=f"(eh) : "f"(hi));
    return pk(el, eh);
}
__device__ __forceinline__ ull rcp2(ull a) {    // elementwise 1/x on packed pair
    float lo, hi; asm("mov.b64 {%0, %1}, %2;" : "=f"(lo), "=f"(hi) : "l"(a));
    float el, eh;
    asm("rcp.approx.f32 %0, %1;" : "=f"(el) : "f"(lo));
    asm("rcp.approx.f32 %0, %1;" : "=f"(eh) : "f"(hi));
    return pk(el, eh);
}

// One LSTM unit update for a packed pair. acc[] already hold -log2e * preact
// (gate g: -2log2e * preact), so E = ex2(acc) = exp(-x) directly.
// Four sigmoids share one reciprocal: s = 1/(1+E) via product-of-denominators.
__device__ __forceinline__ void lstm_unit(const ull acc[4], ull& c, ull& hout,
                                          ull CN2L2E, ull CONE, ull CTWO, ull CNONE)
{
    ull Ei = ex2_2(acc[0]);
    ull Ef = ex2_2(acc[1]);
    ull Eg = ex2_2(acc[2]);             // e^{-2g}
    ull Eo = ex2_2(acc[3]);
    ull Ai = add2(Ei, CONE), Bf = add2(Ef, CONE);
    ull Cg = add2(Eg, CONE), Do = add2(Eo, CONE);
    ull t1 = mul2(Ai, Bf), t2 = mul2(Cg, Do);
    ull r  = rcp2(mul2(t1, t2));
    ull q1 = mul2(r, t2), q2 = mul2(r, t1);
    ull si = mul2(q1, Bf);              // sigmoid(i)
    ull sf = mul2(q1, Ai);              // sigmoid(f)
    ull sg = mul2(q2, Do);              // sigmoid(2g)
    ull so = mul2(q2, Cg);              // sigmoid(o)
    ull tg = fma2(sg, CTWO, CNONE);     // tanh(g) = 2*sigmoid(2g) - 1
    c = fma2(sf, c, mul2(si, tg));      // c' = sig(f)*c + sig(i)*tanh(g)
    ull Ec = ex2_2(mul2(c, CN2L2E));    // e^{-2c}
    ull rc = rcp2(add2(Ec, CONE));      // sigmoid(2c)
    ull tc = fma2(rc, CTWO, CNONE);     // tanh(c)
    hout = mul2(so, tc);
}

// Load 2 consecutive rows of a [B,8] tensor and pack into 1 pair x 8 features
__device__ __forceinline__ void load_pack_state(const float* __restrict__ base, int e0, ull p[8])
{
    const float4* q = (const float4*)(base + (size_t)e0 * 8);
    float4 a0 = q[0], a1 = q[1];   // row e0
    float4 b0 = q[2], b1 = q[3];   // row e0+1
    p[0] = pk(a0.x, b0.x); p[1] = pk(a0.y, b0.y); p[2] = pk(a0.z, b0.z); p[3] = pk(a0.w, b0.w);
    p[4] = pk(a1.x, b1.x); p[5] = pk(a1.y, b1.y); p[6] = pk(a1.z, b1.z); p[7] = pk(a1.w, b1.w);
}

// out[a*B + b] = h[b][a]  (the transpose().reshape in the reference) — coalesced STG.64
__device__ __forceinline__ void store_h(float* __restrict__ out, int e0, ull hp[8])
{
    #pragma unroll
    for (int a = 0; a < 8; a++)
        *(ull*)(out + (size_t)a * NB + e0) = hp[a];
}

template<int TSTEPS, int PH>
__device__ __forceinline__ void run_phase(const Wpack& sP,
    const float* __restrict__ xbase, int e0,
    ull hp[8], ull cp[8],
    ull CN2L2E, ull CONE, ull CTWO, ull CNONE)
{
    const float4* xp = (const float4*)(xbase + (size_t)e0 * 2);
    const size_t S4 = (size_t)NB * 2 / 4;   // float4 stride per timestep
    float4 xA = xp[0];                      // prefetch t=0

    #pragma unroll 1
    for (int t = 0; t < TSTEPS; t++) {
        ull px[2];
        px[0] = pk(xA.x, xA.z);             // feature 0 of elems e0, e0+1
        px[1] = pk(xA.y, xA.w);             // feature 1
        if (t + 1 < TSTEPS) xA = xp[(size_t)(t + 1) * S4];

        ull hn[8];
        #pragma unroll
        for (int j = 0; j < 8; j++) {
            ull acc[4];
            {
                const ulonglong2* bz = (const ulonglong2*)&sP.Bz[PH][j][0];
                ulonglong2 b01 = bz[0], b23 = bz[1];
                acc[0] = b01.x; acc[1] = b01.y; acc[2] = b23.x; acc[3] = b23.y;
            }
            #pragma unroll
            for (int m = 0; m < 2; m++) {
                const ulonglong2* aw = (const ulonglong2*)&sP.A[PH][j][m][0];
                ulonglong2 w01 = aw[0], w23 = aw[1];
                acc[0] = fma2(w01.x, px[m], acc[0]);
                acc[1] = fma2(w01.y, px[m], acc[1]);
                acc[2] = fma2(w23.x, px[m], acc[2]);
                acc[3] = fma2(w23.y, px[m], acc[3]);
            }
            #pragma unroll
            for (int k = 0; k < 8; k++) {
                const ulonglong2* ww = (const ulonglong2*)&sP.W[PH][j][k][0];
                ulonglong2 w01 = ww[0], w23 = ww[1];
                ull hk = hp[k];
                acc[0] = fma2(w01.x, hk, acc[0]);
                acc[1] = fma2(w01.y, hk, acc[1]);
                acc[2] = fma2(w23.x, hk, acc[2]);
                acc[3] = fma2(w23.y, hk, acc[3]);
            }
            lstm_unit(acc, cp[j], hn[j], CN2L2E, CONE, CTWO, CNONE);
        }
        #pragma unroll
        for (int j = 0; j < 8; j++) hp[j] = hn[j];
    }
}

__global__ void __launch_bounds__(128, 5)
enc_kernel(const float* __restrict__ obs, const float* __restrict__ pre,
           const float* __restrict__ h0, const float* __restrict__ c0,
           const float* __restrict__ c0p, float* __restrict__ out)
{
    __shared__ Wpack sP;
    {
        const float2* src = (const float2*)&gPack;
        float2* dst = (float2*)&sP;
        #pragma unroll 2
        for (int i = threadIdx.x; i < (int)(sizeof(Wpack) / sizeof(float2)); i += 128)
            dst[i] = src[i];
    }
    __syncthreads();

    const int tid = blockIdx.x * 128 + threadIdx.x;
    const int e0 = tid * 2;                  // 2 batch elements (one packed pair) per thread

    const ull CN2L2E = pk(-2.8853900817779268f, -2.8853900817779268f);
    const ull CONE   = pk(1.0f, 1.0f);
    const ull CTWO   = pk(2.0f, 2.0f);
    const ull CNONE  = pk(-1.0f, -1.0f);

    ull hp[8], cp[8];
    load_pack_state(h0, e0, hp);
    load_pack_state(c0, e0, cp);

    run_phase<T_OBS, 0>(sP, obs, e0, hp, cp, CN2L2E, CONE, CTWO, CNONE);
    store_h(out, e0, hp);                    // c_out = transpose(h_obs)

    load_pack_state(c0p, e0, cp);            // cell state re-init; h carries over
    run_phase<T_PRE, 1>(sP, pre, e0, hp, cp, CN2L2E, CONE, CTWO, CNONE);
    store_h(out + (size_t)NB * 8, e0, hp);   // x_out = transpose(h_pre)
}

extern "C" void kernel_launch(void* const* d_in, const int* in_sizes, int n_in,
                              void* d_out, int out_size)
{
    const float* obs   = (const float*)d_in[0];
    const float* pre   = (const float*)d_in[1];
    const float* h0    = (const float*)d_in[2];
    const float* c0    = (const float*)d_in[3];
    const float* c0p   = (const float*)d_in[4];
    const float* W_in  = (const float*)d_in[5];
    const float* b_in  = (const float*)d_in[6];
    const float* Wih_o = (const float*)d_in[7];
    const float* Whh_o = (const float*)d_in[8];
    const float* bih_o = (const float*)d_in[9];
    const float* bhh_o = (const float*)d_in[10];
    const float* Wih_p = (const float*)d_in[11];
    const float* Whh_p = (const float*)d_in[12];
    const float* bih_p = (const float*)d_in[13];
    const float* bhh_p = (const float*)d_in[14];

    prep_kernel<<<1, 64>>>(W_in, b_in, Wih_o, Whh_o, bih_o, bhh_o,
                           Wih_p, Whh_p, bih_p, bhh_p);
    enc_kernel<<<NB / 2 / 128, 128>>>(obs, pre, h0, c0, c0p, (float*)d_out);
}

// round 3
// speedup vs baseline: 1.5836x; 1.5836x over previous
#include <cuda_runtime.h>

#define NB 524288
#define T_OBS 8
#define T_PRE 12
#define HH 8
#define EE 16

typedef unsigned long long ull;

// Duplicated (w,w) packed weights, pre-scaled by -log2e (gate g: -2*log2e)
struct __align__(16) Wpack {
    float2 W[2][8][8][4];   // [phase][j][k][gate]
    float2 A[2][8][2][4];   // [phase][j][m][gate]   (A = W_ih @ W_in, folded)
    float2 Bz[2][8][4];     // [phase][j][gate]      (b_ih + b_hh + W_ih@b_in, folded)
};
__device__ Wpack gPack;

// ---------------- prep: fold embedding into gate weights, scale, duplicate ----------------
__global__ void prep_kernel(
    const float* __restrict__ W_in, const float* __restrict__ b_in,
    const float* __restrict__ Wih_o, const float* __restrict__ Whh_o,
    const float* __restrict__ bih_o, const float* __restrict__ bhh_o,
    const float* __restrict__ Wih_p, const float* __restrict__ Whh_p,
    const float* __restrict__ bih_p, const float* __restrict__ bhh_p)
{
    int t = threadIdx.x;
    if (t >= 64) return;
    int ph = t >> 5, r = t & 31;
    const float* Wih = ph ? Wih_p : Wih_o;
    const float* Whh = ph ? Whh_p : Whh_o;
    const float* bih = ph ? bih_p : bih_o;
    const float* bhh = ph ? bhh_p : bhh_o;
    int g = r >> 3, j = r & 7;                       // rows: i(0-7) f(8-15) g(16-23) o(24-31)
    const float L2E = 1.4426950408889634f;
    float sc = (g == 2) ? (-2.0f * L2E) : (-L2E);    // fold sigmoid/tanh arg scaling into weights
    float a0 = 0.f, a1 = 0.f, bb = bih[r] + bhh[r];
    for (int e = 0; e < EE; e++) {
        float w = Wih[r * EE + e];
        a0 += w * W_in[e * 2 + 0];
        a1 += w * W_in[e * 2 + 1];
        bb += w * b_in[e];
    }
    a0 *= sc; a1 *= sc; bb *= sc;
    gPack.A[ph][j][0][g] = make_float2(a0, a0);
    gPack.A[ph][j][1][g] = make_float2(a1, a1);
    gPack.Bz[ph][j][g]   = make_float2(bb, bb);
    for (int k = 0; k < HH; k++) {
        float w = Whh[r * HH + k] * sc;
        gPack.W[ph][j][k][g] = make_float2(w, w);
    }
}

// ---------------- packed f32x2 helpers ----------------
__device__ __forceinline__ ull fma2(ull a, ull b, ull c) {
    ull d; asm("fma.rn.f32x2 %0, %1, %2, %3;" : "=l"(d) : "l"(a), "l"(b), "l"(c)); return d;
}
__device__ __forceinline__ ull mul2(ull a, ull b) {
    ull d; asm("mul.rn.f32x2 %0, %1, %2;" : "=l"(d) : "l"(a), "l"(b)); return d;
}
__device__ __forceinline__ ull add2(ull a, ull b) {
    ull d; asm("add.rn.f32x2 %0, %1, %2;" : "=l"(d) : "l"(a), "l"(b)); return d;
}
__device__ __forceinline__ ull pk(float lo, float hi) {
    ull d; asm("mov.b64 %0, {%1, %2};" : "=l"(d) : "f"(lo), "f"(hi)); return d;
}
__device__ __forceinline__ ull ex2_2(ull a) {   // elementwise 2^x on packed pair
    float lo, hi; asm("mov.b64 {%0, %1}, %2;" : "=f"(lo), "=f"(hi) : "l"(a));
    float el, eh;
    asm("ex2.approx.f32 %0, %1;" : "=f"(el) : "f"(lo));
    asm("ex2.approx.f32 %0, %1;" : "=f"(eh) : "f"(hi));
    return pk(el, eh);
}
__device__ __forceinline__ ull rcp2(ull a) {    // elementwise 1/x on packed pair
    float lo, hi; asm("mov.b64 {%0, %1}, %2;" : "=f"(lo), "=f"(hi) : "l"(a));
    float el, eh;
    asm("rcp.approx.f32 %0, %1;" : "=f"(el) : "f"(lo));
    asm("rcp.approx.f32 %0, %1;" : "=f"(eh) : "f"(hi));
    return pk(el, eh);
}
__device__ __forceinline__ ull shfl4(ull v, int src) {  // shuffle within 4-lane group
    return __shfl_sync(0xffffffffu, v, src, 4);
}

// One LSTM unit update for a packed pair. acc[] already hold -log2e * preact
// (gate g: -2log2e * preact). Four sigmoids share one reciprocal.
__device__ __forceinline__ void lstm_unit(const ull acc[4], ull& c, ull& hout,
                                          ull CN2L2E, ull CONE, ull CTWO, ull CNONE)
{
    ull Ei = ex2_2(acc[0]);
    ull Ef = ex2_2(acc[1]);
    ull Eg = ex2_2(acc[2]);             // e^{-2g}
    ull Eo = ex2_2(acc[3]);
    ull Ai = add2(Ei, CONE), Bf = add2(Ef, CONE);
    ull Cg = add2(Eg, CONE), Do = add2(Eo, CONE);
    ull t1 = mul2(Ai, Bf), t2 = mul2(Cg, Do);
    ull r  = rcp2(mul2(t1, t2));
    ull q1 = mul2(r, t2), q2 = mul2(r, t1);
    ull si = mul2(q1, Bf);              // sigmoid(i)
    ull sf = mul2(q1, Ai);              // sigmoid(f)
    ull sg = mul2(q2, Do);              // sigmoid(2g)
    ull so = mul2(q2, Cg);              // sigmoid(o)
    ull tg = fma2(sg, CTWO, CNONE);     // tanh(g) = 2*sigmoid(2g) - 1
    c = fma2(sf, c, mul2(si, tg));      // c' = sig(f)*c + sig(i)*tanh(g)
    ull Ec = ex2_2(mul2(c, CN2L2E));    // e^{-2c}
    ull rc = rcp2(add2(Ec, CONE));      // sigmoid(2c)
    ull tc = fma2(rc, CTWO, CNONE);     // tanh(c)
    hout = mul2(so, tc);
}

// Load this thread's 2 units (2u, 2u+1) of its pair (e0, e0+1) from a [B,8] tensor
__device__ __forceinline__ void load_state2(const float* __restrict__ base, int e0, int u, ull p[2])
{
    float2 fa = *(const float2*)(base + (size_t)e0 * 8 + 2 * u);
    float2 fb = *(const float2*)(base + (size_t)(e0 + 1) * 8 + 2 * u);
    p[0] = pk(fa.x, fb.x);
    p[1] = pk(fa.y, fb.y);
}

template<int TSTEPS, int PH>
__device__ __forceinline__ void run_phase(const Wpack& sP,
    const float* __restrict__ xbase, int P, int u,
    ull hp[2], ull cp[2],
    ull CN2L2E, ull CONE, ull CTWO, ull CNONE)
{
    // x[t] for this pair: float4 at (t*NB + 2P)*2 floats = float4 index t*(NB/2) + P
    const float4* xp = (const float4*)xbase + (size_t)P;
    const size_t S4 = (size_t)NB / 2;       // float4 stride per timestep
    float4 xA = xp[0];                      // prefetch t=0
    const int j0 = 2 * u, j1 = 2 * u + 1;

    #pragma unroll 1
    for (int t = 0; t < TSTEPS; t++) {
        ull px[2];
        px[0] = pk(xA.x, xA.z);             // feature 0 of elems e0, e0+1
        px[1] = pk(xA.y, xA.w);             // feature 1
        if (t + 1 < TSTEPS) xA = xp[(size_t)(t + 1) * S4];

        ull acc0[4], acc1[4];
        {
            const ulonglong2* b0 = (const ulonglong2*)&sP.Bz[PH][j0][0];
            const ulonglong2* b1 = (const ulonglong2*)&sP.Bz[PH][j1][0];
            ulonglong2 a01 = b0[0], a23 = b0[1], c01 = b1[0], c23 = b1[1];
            acc0[0] = a01.x; acc0[1] = a01.y; acc0[2] = a23.x; acc0[3] = a23.y;
            acc1[0] = c01.x; acc1[1] = c01.y; acc1[2] = c23.x; acc1[3] = c23.y;
        }
        #pragma unroll
        for (int m = 0; m < 2; m++) {
            const ulonglong2* a0 = (const ulonglong2*)&sP.A[PH][j0][m][0];
            const ulonglong2* a1 = (const ulonglong2*)&sP.A[PH][j1][m][0];
            ulonglong2 w01 = a0[0], w23 = a0[1];
            ulonglong2 v01 = a1[0], v23 = a1[1];
            acc0[0] = fma2(w01.x, px[m], acc0[0]);
            acc0[1] = fma2(w01.y, px[m], acc0[1]);
            acc0[2] = fma2(w23.x, px[m], acc0[2]);
            acc0[3] = fma2(w23.y, px[m], acc0[3]);
            acc1[0] = fma2(v01.x, px[m], acc1[0]);
            acc1[1] = fma2(v01.y, px[m], acc1[1]);
            acc1[2] = fma2(v23.x, px[m], acc1[2]);
            acc1[3] = fma2(v23.y, px[m], acc1[3]);
        }
        // h gather across the 4-lane group: lane kk owns h for units 2kk, 2kk+1
        #pragma unroll
        for (int kk = 0; kk < 4; kk++) {
            ull ha = shfl4(hp[0], kk);       // h_{2kk}
            ull hb = shfl4(hp[1], kk);       // h_{2kk+1}
            const ulonglong2* wa0 = (const ulonglong2*)&sP.W[PH][j0][2 * kk][0];
            const ulonglong2* wb0 = (const ulonglong2*)&sP.W[PH][j0][2 * kk + 1][0];
            const ulonglong2* wa1 = (const ulonglong2*)&sP.W[PH][j1][2 * kk][0];
            const ulonglong2* wb1 = (const ulonglong2*)&sP.W[PH][j1][2 * kk + 1][0];
            ulonglong2 p01 = wa0[0], p23 = wa0[1];
            ulonglong2 q01 = wb0[0], q23 = wb0[1];
            ulonglong2 r01 = wa1[0], r23 = wa1[1];
            ulonglong2 s01 = wb1[0], s23 = wb1[1];
            acc0[0] = fma2(p01.x, ha, acc0[0]); acc0[0] = fma2(q01.x, hb, acc0[0]);
            acc0[1] = fma2(p01.y, ha, acc0[1]); acc0[1] = fma2(q01.y, hb, acc0[1]);
            acc0[2] = fma2(p23.x, ha, acc0[2]); acc0[2] = fma2(q23.x, hb, acc0[2]);
            acc0[3] = fma2(p23.y, ha, acc0[3]); acc0[3] = fma2(q23.y, hb, acc0[3]);
            acc1[0] = fma2(r01.x, ha, acc1[0]); acc1[0] = fma2(s01.x, hb, acc1[0]);
            acc1[1] = fma2(r01.y, ha, acc1[1]); acc1[1] = fma2(s01.y, hb, acc1[1]);
            acc1[2] = fma2(r23.x, ha, acc1[2]); acc1[2] = fma2(s23.x, hb, acc1[2]);
            acc1[3] = fma2(r23.y, ha, acc1[3]); acc1[3] = fma2(s23.y, hb, acc1[3]);
        }
        ull hn0, hn1;
        lstm_unit(acc0, cp[0], hn0, CN2L2E, CONE, CTWO, CNONE);
        lstm_unit(acc1, cp[1], hn1, CN2L2E, CONE, CTWO, CNONE);
        hp[0] = hn0; hp[1] = hn1;
    }
}

__global__ void __launch_bounds__(128, 6)
enc_kernel(const float* __restrict__ obs, const float* __restrict__ pre,
           const float* __restrict__ h0, const float* __restrict__ c0,
           const float* __restrict__ c0p, float* __restrict__ out)
{
    __shared__ Wpack sP;
    {
        const float2* src = (const float2*)&gPack;
        float2* dst = (float2*)&sP;
        #pragma unroll 2
        for (int i = threadIdx.x; i < (int)(sizeof(Wpack) / sizeof(float2)); i += 128)
            dst[i] = src[i];
    }
    __syncthreads();

    // warp = 8 pairs = 16 elements; lane = p*4 + u
    const int lane = threadIdx.x & 31;
    const int warp = threadIdx.x >> 5;
    const int p = lane >> 2;                 // pair within warp (0..7)
    const int u = lane & 3;                  // unit group: units 2u, 2u+1
    const int gw = blockIdx.x * 4 + warp;    // global warp index
    const int P  = gw * 8 + p;               // global pair index
    const int e0 = 2 * P;                    // first element of the pair

    const ull CN2L2E = pk(-2.8853900817779268f, -2.8853900817779268f);
    const ull CONE   = pk(1.0f, 1.0f);
    const ull CTWO   = pk(2.0f, 2.0f);
    const ull CNONE  = pk(-1.0f, -1.0f);

    ull hp[2], cp[2];
    load_state2(h0, e0, u, hp);
    load_state2(c0, e0, u, cp);

    run_phase<T_OBS, 0>(sP, obs, P, u, hp, cp, CN2L2E, CONE, CTWO, CNONE);
    // c_out = transpose(h_obs): out[a*B + b]
    *(ull*)(out + (size_t)(2 * u + 0) * NB + e0) = hp[0];
    *(ull*)(out + (size_t)(2 * u + 1) * NB + e0) = hp[1];

    load_state2(c0p, e0, u, cp);             // cell re-init; h carries over
    run_phase<T_PRE, 1>(sP, pre, P, u, hp, cp, CN2L2E, CONE, CTWO, CNONE);
    float* out2 = out + (size_t)NB * 8;
    *(ull*)(out2 + (size_t)(2 * u + 0) * NB + e0) = hp[0];
    *(ull*)(out2 + (size_t)(2 * u + 1) * NB + e0) = hp[1];
}

extern "C" void kernel_launch(void* const* d_in, const int* in_sizes, int n_in,
                              void* d_out, int out_size)
{
    const float* obs   = (const float*)d_in[0];
    const float* pre   = (const float*)d_in[1];
    const float* h0    = (const float*)d_in[2];
    const float* c0    = (const float*)d_in[3];
    const float* c0p   = (const float*)d_in[4];
    const float* W_in  = (const float*)d_in[5];
    const float* b_in  = (const float*)d_in[6];
    const float* Wih_o = (const float*)d_in[7];
    const float* Whh_o = (const float*)d_in[8];
    const float* bih_o = (const float*)d_in[9];
    const float* bhh_o = (const float*)d_in[10];
    const float* Wih_p = (const float*)d_in[11];
    const float* Whh_p = (const float*)d_in[12];
    const float* bih_p = (const float*)d_in[13];
    const float* bhh_p = (const float*)d_in[14];

    prep_kernel<<<1, 64>>>(W_in, b_in, Wih_o, Whh_o, bih_o, bhh_o,
                           Wih_p, Whh_p, bih_p, bhh_p);
    // 1 warp = 16 elems, 4 warps/block -> 64 elems/block
    enc_kernel<<<NB / 64, 128>>>(obs, pre, h0, c0, c0p, (float*)d_out);
}

// round 6
// speedup vs baseline: 3.3028x; 2.0857x over previous
#include <cuda_runtime.h>

#define NB 524288
#define T_OBS 8
#define T_PRE 12
#define HH 8
#define EE 16

typedef unsigned long long ull;

// Duplicated (w,w) packed weights, pre-scaled by -log2e (gate g: -2*log2e)
struct __align__(16) Wpack {
    float2 W[2][8][8][4];   // [phase][j][k][gate]
    float2 A[2][8][2][4];   // [phase][j][m][gate]   (A = W_ih @ W_in, folded)
    float2 Bz[2][8][4];     // [phase][j][gate]      (b_ih + b_hh + W_ih@b_in, folded)
};
__device__ Wpack gPack;

// ---------------- prep: fold embedding into gate weights, scale, duplicate ----------------
__global__ void prep_kernel(
    const float* __restrict__ W_in, const float* __restrict__ b_in,
    const float* __restrict__ Wih_o, const float* __restrict__ Whh_o,
    const float* __restrict__ bih_o, const float* __restrict__ bhh_o,
    const float* __restrict__ Wih_p, const float* __restrict__ Whh_p,
    const float* __restrict__ bih_p, const float* __restrict__ bhh_p)
{
    int t = threadIdx.x;
    if (t >= 64) return;
    int ph = t >> 5, r = t & 31;
    const float* Wih = ph ? Wih_p : Wih_o;
    const float* Whh = ph ? Whh_p : Whh_o;
    const float* bih = ph ? bih_p : bih_o;
    const float* bhh = ph ? bhh_p : bhh_o;
    int g = r >> 3, j = r & 7;                       // rows: i(0-7) f(8-15) g(16-23) o(24-31)
    const float L2E = 1.4426950408889634f;
    float sc = (g == 2) ? (-2.0f * L2E) : (-L2E);    // fold sigmoid/tanh arg scaling into weights
    float a0 = 0.f, a1 = 0.f, bb = bih[r] + bhh[r];
    for (int e = 0; e < EE; e++) {
        float w = Wih[r * EE + e];
        a0 += w * W_in[e * 2 + 0];
        a1 += w * W_in[e * 2 + 1];
        bb += w * b_in[e];
    }
    a0 *= sc; a1 *= sc; bb *= sc;
    gPack.A[ph][j][0][g] = make_float2(a0, a0);
    gPack.A[ph][j][1][g] = make_float2(a1, a1);
    gPack.Bz[ph][j][g]   = make_float2(bb, bb);
    for (int k = 0; k < HH; k++) {
        float w = Whh[r * HH + k] * sc;
        gPack.W[ph][j][k][g] = make_float2(w, w);
    }
}

// ---------------- packed f32x2 helpers ----------------
__device__ __forceinline__ ull fma2(ull a, ull b, ull c) {
    ull d; asm("fma.rn.f32x2 %0, %1, %2, %3;" : "=l"(d) : "l"(a), "l"(b), "l"(c)); return d;
}
__device__ __forceinline__ ull mul2(ull a, ull b) {
    ull d; asm("mul.rn.f32x2 %0, %1, %2;" : "=l"(d) : "l"(a), "l"(b)); return d;
}
__device__ __forceinline__ ull add2(ull a, ull b) {
    ull d; asm("add.rn.f32x2 %0, %1, %2;" : "=l"(d) : "l"(a), "l"(b)); return d;
}
__device__ __forceinline__ ull pk(float lo, float hi) {
    ull d; asm("mov.b64 %0, {%1, %2};" : "=l"(d) : "f"(lo), "f"(hi)); return d;
}
__device__ __forceinline__ ull ex2_2(ull a) {   // elementwise 2^x on packed pair
    float lo, hi; asm("mov.b64 {%0, %1}, %2;" : "=f"(lo), "=f"(hi) : "l"(a));
    float el, eh;
    asm("ex2.approx.f32 %0, %1;" : "=f"(el) : "f"(lo));
    asm("ex2.approx.f32 %0, %1;" : "=f"(eh) : "f"(hi));
    return pk(el, eh);
}
__device__ __forceinline__ ull rcp2(ull a) {    // elementwise 1/x on packed pair
    float lo, hi; asm("mov.b64 {%0, %1}, %2;" : "=f"(lo), "=f"(hi) : "l"(a));
    float el, eh;
    asm("rcp.approx.f32 %0, %1;" : "=f"(el) : "f"(lo));
    asm("rcp.approx.f32 %0, %1;" : "=f"(eh) : "f"(hi));
    return pk(el, eh);
}
__device__ __forceinline__ ull shfl8(ull v, int src) {  // shuffle within 8-lane group
    return __shfl_sync(0xffffffffu, v, src, 8);
}

// One LSTM unit update for a packed pair. acc[] already hold -log2e * preact
// (gate g: -2log2e * preact). Four sigmoids share one reciprocal.
__device__ __forceinline__ void lstm_unit(const ull acc[4], ull& c, ull& hout,
                                          ull CN2L2E, ull CONE, ull CTWO, ull CNONE)
{
    ull Ei = ex2_2(acc[0]);
    ull Ef = ex2_2(acc[1]);
    ull Eg = ex2_2(acc[2]);             // e^{-2g}
    ull Eo = ex2_2(acc[3]);
    ull Ai = add2(Ei, CONE), Bf = add2(Ef, CONE);
    ull Cg = add2(Eg, CONE), Do = add2(Eo, CONE);
    ull t1 = mul2(Ai, Bf), t2 = mul2(Cg, Do);
    ull r  = rcp2(mul2(t1, t2));
    ull q1 = mul2(r, t2), q2 = mul2(r, t1);
    ull si = mul2(q1, Bf);              // sigmoid(i)
    ull sf = mul2(q1, Ai);              // sigmoid(f)
    ull sg = mul2(q2, Do);              // sigmoid(2g)
    ull so = mul2(q2, Cg);              // sigmoid(o)
    ull tg = fma2(sg, CTWO, CNONE);     // tanh(g) = 2*sigmoid(2g) - 1
    c = fma2(sf, c, mul2(si, tg));      // c' = sig(f)*c + sig(i)*tanh(g)
    ull Ec = ex2_2(mul2(c, CN2L2E));    // e^{-2c}
    ull rc = rcp2(add2(Ec, CONE));      // sigmoid(2c)
    ull tc = fma2(rc, CTWO, CNONE);     // tanh(c)
    hout = mul2(so, tc);
}

template<int TSTEPS, int PH>
__device__ __forceinline__ void run_phase(const Wpack& sP,
    const float* __restrict__ xbase, int P, int u,
    ull& hp, ull& cp,
    ull CN2L2E, ull CONE, ull CTWO, ull CNONE)
{
    // ---- load this unit's recurrent weights into registers (phase-resident) ----
    ull Wr[8][4];
    #pragma unroll
    for (int k = 0; k < 8; k++) {
        const ulonglong2* ww = (const ulonglong2*)&sP.W[PH][u][k][0];
        ulonglong2 q01 = ww[0], q23 = ww[1];
        Wr[k][0] = q01.x; Wr[k][1] = q01.y; Wr[k][2] = q23.x; Wr[k][3] = q23.y;
    }

    // x[t] for this pair: float4 index t*(NB/2) + P
    const float4* xp = (const float4*)xbase + (size_t)P;
    const size_t S4 = (size_t)NB / 2;       // float4 stride per timestep
    float4 xA = xp[0];                      // prefetch t=0

    #pragma unroll 1
    for (int t = 0; t < TSTEPS; t++) {
        ull px0 = pk(xA.x, xA.z);           // feature 0 of elems e0, e0+1
        ull px1 = pk(xA.y, xA.w);           // feature 1
        if (t + 1 < TSTEPS) xA = xp[(size_t)(t + 1) * S4];

        // acc init = Bz + A@x  (Bz, A streamed from smem — off the h-critical path)
        ull acc[4];
        {
            const ulonglong2* bz = (const ulonglong2*)&sP.Bz[PH][u][0];
            ulonglong2 b01 = bz[0], b23 = bz[1];
            const ulonglong2* a0 = (const ulonglong2*)&sP.A[PH][u][0][0];
            const ulonglong2* a1 = (const ulonglong2*)&sP.A[PH][u][1][0];
            ulonglong2 w01 = a0[0], w23 = a0[1];
            ulonglong2 v01 = a1[0], v23 = a1[1];
            acc[0] = fma2(w01.x, px0, b01.x); acc[0] = fma2(v01.x, px1, acc[0]);
            acc[1] = fma2(w01.y, px0, b01.y); acc[1] = fma2(v01.y, px1, acc[1]);
            acc[2] = fma2(w23.x, px0, b23.x); acc[2] = fma2(v23.x, px1, acc[2]);
            acc[3] = fma2(w23.y, px0, b23.y); acc[3] = fma2(v23.y, px1, acc[3]);
        }

        // recurrent part: h broadcast across the 8-lane group, weights from registers
        #pragma unroll
        for (int k = 0; k < 8; k++) {
            ull hk = shfl8(hp, k);
            acc[0] = fma2(Wr[k][0], hk, acc[0]);
            acc[1] = fma2(Wr[k][1], hk, acc[1]);
            acc[2] = fma2(Wr[k][2], hk, acc[2]);
            acc[3] = fma2(Wr[k][3], hk, acc[3]);
        }

        lstm_unit(acc, cp, hp, CN2L2E, CONE, CTWO, CNONE);
    }
}

__global__ void __launch_bounds__(128, 4)
enc_kernel(const float* __restrict__ obs, const float* __restrict__ pre,
           const float* __restrict__ h0, const float* __restrict__ c0,
           const float* __restrict__ c0p, float* __restrict__ out)
{
    __shared__ Wpack sP;
    {
        const float2* src = (const float2*)&gPack;
        float2* dst = (float2*)&sP;
        #pragma unroll 2
        for (int i = threadIdx.x; i < (int)(sizeof(Wpack) / sizeof(float2)); i += 128)
            dst[i] = src[i];
    }
    __syncthreads();

    // warp = 4 pairs = 8 elements; lane = p*8 + u  (u = hidden unit, p = pair)
    const int lane = threadIdx.x & 31;
    const int warp = threadIdx.x >> 5;
    const int p = lane >> 3;                 // pair within warp (0..3)
    const int u = lane & 7;                  // hidden unit (0..7)
    const int gw = blockIdx.x * 4 + warp;    // global warp index
    const int P  = gw * 4 + p;               // global pair index
    const int e0 = 2 * P;                    // first element of the pair

    const ull CN2L2E = pk(-2.8853900817779268f, -2.8853900817779268f);
    const ull CONE   = pk(1.0f, 1.0f);
    const ull CTWO   = pk(2.0f, 2.0f);
    const ull CNONE  = pk(-1.0f, -1.0f);

    // initial state for this unit of the pair: [B,8] layout, stride 8
    ull hp = pk(h0[(size_t)e0 * 8 + u], h0[(size_t)(e0 + 1) * 8 + u]);
    ull cp = pk(c0[(size_t)e0 * 8 + u], c0[(size_t)(e0 + 1) * 8 + u]);

    run_phase<T_OBS, 0>(sP, obs, P, u, hp, cp, CN2L2E, CONE, CTWO, CNONE);
    // c_out = transpose(h_obs): out[u*B + b], 2 consecutive b per thread
    *(ull*)(out + (size_t)u * NB + e0) = hp;

    cp = pk(c0p[(size_t)e0 * 8 + u], c0p[(size_t)(e0 + 1) * 8 + u]);  // cell re-init
    run_phase<T_PRE, 1>(sP, pre, P, u, hp, cp, CN2L2E, CONE, CTWO, CNONE);
    *(ull*)(out + (size_t)NB * 8 + (size_t)u * NB + e0) = hp;
}

extern "C" void kernel_launch(void* const* d_in, const int* in_sizes, int n_in,
                              void* d_out, int out_size)
{
    const float* obs   = (const float*)d_in[0];
    const float* pre   = (const float*)d_in[1];
    const float* h0    = (const float*)d_in[2];
    const float* c0    = (const float*)d_in[3];
    const float* c0p   = (const float*)d_in[4];
    const float* W_in  = (const float*)d_in[5];
    const float* b_in  = (const float*)d_in[6];
    const float* Wih_o = (const float*)d_in[7];
    const float* Whh_o = (const float*)d_in[8];
    const float* bih_o = (const float*)d_in[9];
    const float* bhh_o = (const float*)d_in[10];
    const float* Wih_p = (const float*)d_in[11];
    const float* Whh_p = (const float*)d_in[12];
    const float* bih_p = (const float*)d_in[13];
    const float* bhh_p = (const float*)d_in[14];

    prep_kernel<<<1, 64>>>(W_in, b_in, Wih_o, Whh_o, bih_o, bhh_o,
                           Wih_p, Whh_p, bih_p, bhh_p);
    // 1 warp = 8 elems, 4 warps/block -> 32 elems/block
    enc_kernel<<<NB / 32, 128>>>(obs, pre, h0, c0, c0p, (float*)d_out);
}

// round 7
// speedup vs baseline: 3.4856x; 1.0553x over previous
#include <cuda_runtime.h>

#define NB 524288
#define T_OBS 8
#define T_PRE 12
#define HH 8
#define EE 16

typedef unsigned long long ull;

// Duplicated (w,w) packed weights, pre-scaled by -log2e (gate g: -2*log2e)
struct __align__(16) Wpack {
    float2 W[2][8][8][4];   // [phase][j][k][gate]
    float2 A[2][8][2][4];   // [phase][j][m][gate]   (A = W_ih @ W_in, folded)
    float2 Bz[2][8][4];     // [phase][j][gate]      (b_ih + b_hh + W_ih@b_in, folded)
};
__device__ Wpack gPack;

// ---------------- prep: fold embedding into gate weights, scale, duplicate ----------------
__global__ void prep_kernel(
    const float* __restrict__ W_in, const float* __restrict__ b_in,
    const float* __restrict__ Wih_o, const float* __restrict__ Whh_o,
    const float* __restrict__ bih_o, const float* __restrict__ bhh_o,
    const float* __restrict__ Wih_p, const float* __restrict__ Whh_p,
    const float* __restrict__ bih_p, const float* __restrict__ bhh_p)
{
    int t = threadIdx.x;
    if (t >= 64) return;
    int ph = t >> 5, r = t & 31;
    const float* Wih = ph ? Wih_p : Wih_o;
    const float* Whh = ph ? Whh_p : Whh_o;
    const float* bih = ph ? bih_p : bih_o;
    const float* bhh = ph ? bhh_p : bhh_o;
    int g = r >> 3, j = r & 7;                       // rows: i(0-7) f(8-15) g(16-23) o(24-31)
    const float L2E = 1.4426950408889634f;
    float sc = (g == 2) ? (-2.0f * L2E) : (-L2E);    // fold sigmoid/tanh arg scaling into weights
    float a0 = 0.f, a1 = 0.f, bb = bih[r] + bhh[r];
    for (int e = 0; e < EE; e++) {
        float w = Wih[r * EE + e];
        a0 += w * W_in[e * 2 + 0];
        a1 += w * W_in[e * 2 + 1];
        bb += w * b_in[e];
    }
    a0 *= sc; a1 *= sc; bb *= sc;
    gPack.A[ph][j][0][g] = make_float2(a0, a0);
    gPack.A[ph][j][1][g] = make_float2(a1, a1);
    gPack.Bz[ph][j][g]   = make_float2(bb, bb);
    for (int k = 0; k < HH; k++) {
        float w = Whh[r * HH + k] * sc;
        gPack.W[ph][j][k][g] = make_float2(w, w);
    }
}

// ---------------- packed f32x2 helpers ----------------
__device__ __forceinline__ ull fma2(ull a, ull b, ull c) {
    ull d; asm("fma.rn.f32x2 %0, %1, %2, %3;" : "=l"(d) : "l"(a), "l"(b), "l"(c)); return d;
}
__device__ __forceinline__ ull mul2(ull a, ull b) {
    ull d; asm("mul.rn.f32x2 %0, %1, %2;" : "=l"(d) : "l"(a), "l"(b)); return d;
}
__device__ __forceinline__ ull add2(ull a, ull b) {
    ull d; asm("add.rn.f32x2 %0, %1, %2;" : "=l"(d) : "l"(a), "l"(b)); return d;
}
__device__ __forceinline__ ull pk(float lo, float hi) {
    ull d; asm("mov.b64 %0, {%1, %2};" : "=l"(d) : "f"(lo), "f"(hi)); return d;
}
__device__ __forceinline__ ull ex2_2(ull a) {   // elementwise 2^x on packed pair
    float lo, hi; asm("mov.b64 {%0, %1}, %2;" : "=f"(lo), "=f"(hi) : "l"(a));
    float el, eh;
    asm("ex2.approx.f32 %0, %1;" : "=f"(el) : "f"(lo));
    asm("ex2.approx.f32 %0, %1;" : "=f"(eh) : "f"(hi));
    return pk(el, eh);
}
__device__ __forceinline__ ull rcp2(ull a) {    // elementwise 1/x on packed pair
    float lo, hi; asm("mov.b64 {%0, %1}, %2;" : "=f"(lo), "=f"(hi) : "l"(a));
    float el, eh;
    asm("rcp.approx.f32 %0, %1;" : "=f"(el) : "f"(lo));
    asm("rcp.approx.f32 %0, %1;" : "=f"(eh) : "f"(hi));
    return pk(el, eh);
}

// One LSTM unit update for a packed pair. acc[] already hold -log2e * preact
// (gate g: -2log2e * preact). Four sigmoids share one reciprocal.
__device__ __forceinline__ void lstm_unit(const ull acc[4], ull& c, ull& hout,
                                          ull CN2L2E, ull CONE, ull CTWO, ull CNONE)
{
    ull Ei = ex2_2(acc[0]);
    ull Ef = ex2_2(acc[1]);
    ull Eg = ex2_2(acc[2]);             // e^{-2g}
    ull Eo = ex2_2(acc[3]);
    ull Ai = add2(Ei, CONE), Bf = add2(Ef, CONE);
    ull Cg = add2(Eg, CONE), Do = add2(Eo, CONE);
    ull t1 = mul2(Ai, Bf), t2 = mul2(Cg, Do);
    ull r  = rcp2(mul2(t1, t2));
    ull q1 = mul2(r, t2), q2 = mul2(r, t1);
    ull si = mul2(q1, Bf);              // sigmoid(i)
    ull sf = mul2(q1, Ai);              // sigmoid(f)
    ull sg = mul2(q2, Do);              // sigmoid(2g)
    ull so = mul2(q2, Cg);              // sigmoid(o)
    ull tg = fma2(sg, CTWO, CNONE);     // tanh(g) = 2*sigmoid(2g) - 1
    c = fma2(sf, c, mul2(si, tg));      // c' = sig(f)*c + sig(i)*tanh(g)
    ull Ec = ex2_2(mul2(c, CN2L2E));    // e^{-2c}
    ull rc = rcp2(add2(Ec, CONE));      // sigmoid(2c)
    ull tc = fma2(rc, CTWO, CNONE);     // tanh(c)
    hout = mul2(so, tc);
}

// hw: this warp's h-exchange region, 2 buffers x 4 pairs x 8 units (64 ull)
template<int TSTEPS, int PH>
__device__ __forceinline__ void run_phase(const Wpack& sP, ull* hw,
    const float* __restrict__ xbase, int P, int p, int u,
    ull& hp, ull& cp,
    ull CN2L2E, ull CONE, ull CTWO, ull CNONE)
{
    // ---- load this unit's recurrent weights into registers (phase-resident) ----
    ull Wr[8][4];
    #pragma unroll
    for (int k = 0; k < 8; k++) {
        const ulonglong2* ww = (const ulonglong2*)&sP.W[PH][u][k][0];
        ulonglong2 q01 = ww[0], q23 = ww[1];
        Wr[k][0] = q01.x; Wr[k][1] = q01.y; Wr[k][2] = q23.x; Wr[k][3] = q23.y;
    }

    // x[t] for this pair: float4 index t*(NB/2) + P
    const float4* xp = (const float4*)xbase + (size_t)P;
    const size_t S4 = (size_t)NB / 2;       // float4 stride per timestep
    float4 xA = xp[0];                      // prefetch t=0

    // publish initial h into buffer 0
    hw[(p << 3) + u] = hp;
    __syncwarp();

    #pragma unroll 1
    for (int t = 0; t < TSTEPS; t++) {
        ull px0 = pk(xA.x, xA.z);           // feature 0 of elems e0, e0+1
        ull px1 = pk(xA.y, xA.w);           // feature 1
        if (t + 1 < TSTEPS) xA = xp[(size_t)(t + 1) * S4];

        // acc init = Bz + A@x  (Bz, A from smem — broadcast LDS, off critical path)
        ull acc[4];
        {
            const ulonglong2* bz = (const ulonglong2*)&sP.Bz[PH][u][0];
            ulonglong2 b01 = bz[0], b23 = bz[1];
            const ulonglong2* a0 = (const ulonglong2*)&sP.A[PH][u][0][0];
            const ulonglong2* a1 = (const ulonglong2*)&sP.A[PH][u][1][0];
            ulonglong2 w01 = a0[0], w23 = a0[1];
            ulonglong2 v01 = a1[0], v23 = a1[1];
            acc[0] = fma2(w01.x, px0, b01.x); acc[0] = fma2(v01.x, px1, acc[0]);
            acc[1] = fma2(w01.y, px0, b01.y); acc[1] = fma2(v01.y, px1, acc[1]);
            acc[2] = fma2(w23.x, px0, b23.x); acc[2] = fma2(v23.x, px1, acc[2]);
            acc[3] = fma2(w23.y, px0, b23.y); acc[3] = fma2(v23.y, px1, acc[3]);
        }

        // recurrent part: read all 8 h of this pair from smem (4 broadcast LDS.128)
        {
            const ull* hv = hw + ((t & 1) << 5) + (p << 3);
            ulonglong2 h01 = *(const ulonglong2*)(hv + 0);
            ulonglong2 h23 = *(const ulonglong2*)(hv + 2);
            ulonglong2 h45 = *(const ulonglong2*)(hv + 4);
            ulonglong2 h67 = *(const ulonglong2*)(hv + 6);
            acc[0] = fma2(Wr[0][0], h01.x, acc[0]);
            acc[1] = fma2(Wr[0][1], h01.x, acc[1]);
            acc[2] = fma2(Wr[0][2], h01.x, acc[2]);
            acc[3] = fma2(Wr[0][3], h01.x, acc[3]);
            acc[0] = fma2(Wr[1][0], h01.y, acc[0]);
            acc[1] = fma2(Wr[1][1], h01.y, acc[1]);
            acc[2] = fma2(Wr[1][2], h01.y, acc[2]);
            acc[3] = fma2(Wr[1][3], h01.y, acc[3]);
            acc[0] = fma2(Wr[2][0], h23.x, acc[0]);
            acc[1] = fma2(Wr[2][1], h23.x, acc[1]);
            acc[2] = fma2(Wr[2][2], h23.x, acc[2]);
            acc[3] = fma2(Wr[2][3], h23.x, acc[3]);
            acc[0] = fma2(Wr[3][0], h23.y, acc[0]);
            acc[1] = fma2(Wr[3][1], h23.y, acc[1]);
            acc[2] = fma2(Wr[3][2], h23.y, acc[2]);
            acc[3] = fma2(Wr[3][3], h23.y, acc[3]);
            acc[0] = fma2(Wr[4][0], h45.x, acc[0]);
            acc[1] = fma2(Wr[4][1], h45.x, acc[1]);
            acc[2] = fma2(Wr[4][2], h45.x, acc[2]);
            acc[3] = fma2(Wr[4][3], h45.x, acc[3]);
            acc[0] = fma2(Wr[5][0], h45.y, acc[0]);
            acc[1] = fma2(Wr[5][1], h45.y, acc[1]);
            acc[2] = fma2(Wr[5][2], h45.y, acc[2]);
            acc[3] = fma2(Wr[5][3], h45.y, acc[3]);
            acc[0] = fma2(Wr[6][0], h67.x, acc[0]);
            acc[1] = fma2(Wr[6][1], h67.x, acc[1]);
            acc[2] = fma2(Wr[6][2], h67.x, acc[2]);
            acc[3] = fma2(Wr[6][3], h67.x, acc[3]);
            acc[0] = fma2(Wr[7][0], h67.y, acc[0]);
            acc[1] = fma2(Wr[7][1], h67.y, acc[1]);
            acc[2] = fma2(Wr[7][2], h67.y, acc[2]);
            acc[3] = fma2(Wr[7][3], h67.y, acc[3]);
        }

        lstm_unit(acc, cp, hp, CN2L2E, CONE, CTWO, CNONE);

        // publish new h into the other buffer
        if (t + 1 < TSTEPS) {
            hw[(((t + 1) & 1) << 5) + (p << 3) + u] = hp;
            __syncwarp();
        }
    }
}

__global__ void __launch_bounds__(128, 4)
enc_kernel(const float* __restrict__ obs, const float* __restrict__ pre,
           const float* __restrict__ h0, const float* __restrict__ c0,
           const float* __restrict__ c0p, float* __restrict__ out)
{
    __shared__ Wpack sP;
    __shared__ ull hbuf[4][64];              // per-warp: 2 bufs x 4 pairs x 8 units
    {
        const float2* src = (const float2*)&gPack;
        float2* dst = (float2*)&sP;
        #pragma unroll 2
        for (int i = threadIdx.x; i < (int)(sizeof(Wpack) / sizeof(float2)); i += 128)
            dst[i] = src[i];
    }
    __syncthreads();

    // warp = 4 pairs = 8 elements; lane = p*8 + u  (u = hidden unit, p = pair)
    const int lane = threadIdx.x & 31;
    const int warp = threadIdx.x >> 5;
    const int p = lane >> 3;                 // pair within warp (0..3)
    const int u = lane & 7;                  // hidden unit (0..7)
    const int gw = blockIdx.x * 4 + warp;    // global warp index
    const int P  = gw * 4 + p;               // global pair index
    const int e0 = 2 * P;                    // first element of the pair

    const ull CN2L2E = pk(-2.8853900817779268f, -2.8853900817779268f);
    const ull CONE   = pk(1.0f, 1.0f);
    const ull CTWO   = pk(2.0f, 2.0f);
    const ull CNONE  = pk(-1.0f, -1.0f);

    // initial state for this unit of the pair: [B,8] layout, stride 8
    ull hp = pk(h0[(size_t)e0 * 8 + u], h0[(size_t)(e0 + 1) * 8 + u]);
    ull cp = pk(c0[(size_t)e0 * 8 + u], c0[(size_t)(e0 + 1) * 8 + u]);

    run_phase<T_OBS, 0>(sP, hbuf[warp], obs, P, p, u, hp, cp, CN2L2E, CONE, CTWO, CNONE);
    // c_out = transpose(h_obs): out[u*B + b], 2 consecutive b per thread
    *(ull*)(out + (size_t)u * NB + e0) = hp;

    cp = pk(c0p[(size_t)e0 * 8 + u], c0p[(size_t)(e0 + 1) * 8 + u]);  // cell re-init
    run_phase<T_PRE, 1>(sP, hbuf[warp], pre, P, p, u, hp, cp, CN2L2E, CONE, CTWO, CNONE);
    *(ull*)(out + (size_t)NB * 8 + (size_t)u * NB + e0) = hp;
}

extern "C" void kernel_launch(void* const* d_in, const int* in_sizes, int n_in,
                              void* d_out, int out_size)
{
    const float* obs   = (const float*)d_in[0];
    const float* pre   = (const float*)d_in[1];
    const float* h0    = (const float*)d_in[2];
    const float* c0    = (const float*)d_in[3];
    const float* c0p   = (const float*)d_in[4];
    const float* W_in  = (const float*)d_in[5];
    const float* b_in  = (const float*)d_in[6];
    const float* Wih_o = (const float*)d_in[7];
    const float* Whh_o = (const float*)d_in[8];
    const float* bih_o = (const float*)d_in[9];
    const float* bhh_o = (const float*)d_in[10];
    const float* Wih_p = (const float*)d_in[11];
    const float* Whh_p = (const float*)d_in[12];
    const float* bih_p = (const float*)d_in[13];
    const float* bhh_p = (const float*)d_in[14];

    prep_kernel<<<1, 64>>>(W_in, b_in, Wih_o, Whh_o, bih_o, bhh_o,
                           Wih_p, Whh_p, bih_p, bhh_p);
    // 1 warp = 8 elems, 4 warps/block -> 32 elems/block
    enc_kernel<<<NB / 32, 128>>>(obs, pre, h0, c0, c0p, (float*)d_out);
}

// round 8
// speedup vs baseline: 5.8678x; 1.6834x over previous
#include <cuda_runtime.h>

#define NB 524288
#define T_OBS 8
#define T_PRE 12
#define HH 8
#define EE 16

typedef unsigned long long ull;

// Duplicated (w,w) packed weights, pre-scaled by -log2e (gate g: -2*log2e)
struct __align__(16) Wpack {
    float2 W[2][8][8][4];   // [phase][u][k][gate]
    float2 A[2][8][2][4];   // [phase][u][m][gate]   (A = W_ih @ W_in, folded)
    float2 Bz[2][8][4];     // [phase][u][gate]      (b_ih + b_hh + W_ih@b_in, folded)
};
__device__ Wpack gPack;

// ---------------- prep: fold embedding into gate weights, scale, duplicate ----------------
__global__ void prep_kernel(
    const float* __restrict__ W_in, const float* __restrict__ b_in,
    const float* __restrict__ Wih_o, const float* __restrict__ Whh_o,
    const float* __restrict__ bih_o, const float* __restrict__ bhh_o,
    const float* __restrict__ Wih_p, const float* __restrict__ Whh_p,
    const float* __restrict__ bih_p, const float* __restrict__ bhh_p)
{
    int t = threadIdx.x;
    if (t >= 64) return;
    int ph = t >> 5, r = t & 31;
    const float* Wih = ph ? Wih_p : Wih_o;
    const float* Whh = ph ? Whh_p : Whh_o;
    const float* bih = ph ? bih_p : bih_o;
    const float* bhh = ph ? bhh_p : bhh_o;
    int g = r >> 3, j = r & 7;                       // rows: i(0-7) f(8-15) g(16-23) o(24-31)
    const float L2E = 1.4426950408889634f;
    float sc = (g == 2) ? (-2.0f * L2E) : (-L2E);    // fold sigmoid/tanh arg scaling into weights
    float a0 = 0.f, a1 = 0.f, bb = bih[r] + bhh[r];
    for (int e = 0; e < EE; e++) {
        float w = Wih[r * EE + e];
        a0 += w * W_in[e * 2 + 0];
        a1 += w * W_in[e * 2 + 1];
        bb += w * b_in[e];
    }
    a0 *= sc; a1 *= sc; bb *= sc;
    gPack.A[ph][j][0][g] = make_float2(a0, a0);
    gPack.A[ph][j][1][g] = make_float2(a1, a1);
    gPack.Bz[ph][j][g]   = make_float2(bb, bb);
    for (int k = 0; k < HH; k++) {
        float w = Whh[r * HH + k] * sc;
        gPack.W[ph][j][k][g] = make_float2(w, w);
    }
}

// ---------------- packed f32x2 helpers ----------------
__device__ __forceinline__ ull fma2(ull a, ull b, ull c) {
    ull d; asm("fma.rn.f32x2 %0, %1, %2, %3;" : "=l"(d) : "l"(a), "l"(b), "l"(c)); return d;
}
__device__ __forceinline__ ull mul2(ull a, ull b) {
    ull d; asm("mul.rn.f32x2 %0, %1, %2;" : "=l"(d) : "l"(a), "l"(b)); return d;
}
__device__ __forceinline__ ull add2(ull a, ull b) {
    ull d; asm("add.rn.f32x2 %0, %1, %2;" : "=l"(d) : "l"(a), "l"(b)); return d;
}
__device__ __forceinline__ ull pk(float lo, float hi) {
    ull d; asm("mov.b64 %0, {%1, %2};" : "=l"(d) : "f"(lo), "f"(hi)); return d;
}
__device__ __forceinline__ ull ex2_2(ull a) {   // elementwise 2^x on packed pair
    float lo, hi; asm("mov.b64 {%0, %1}, %2;" : "=f"(lo), "=f"(hi) : "l"(a));
    float el, eh;
    asm("ex2.approx.f32 %0, %1;" : "=f"(el) : "f"(lo));
    asm("ex2.approx.f32 %0, %1;" : "=f"(eh) : "f"(hi));
    return pk(el, eh);
}
__device__ __forceinline__ ull rcp2(ull a) {    // elementwise 1/x on packed pair
    float lo, hi; asm("mov.b64 {%0, %1}, %2;" : "=f"(lo), "=f"(hi) : "l"(a));
    float el, eh;
    asm("rcp.approx.f32 %0, %1;" : "=f"(el) : "f"(lo));
    asm("rcp.approx.f32 %0, %1;" : "=f"(eh) : "f"(hi));
    return pk(el, eh);
}

// One LSTM unit update for a packed pair. acc[] already hold -log2e * preact
// (gate g: -2log2e * preact). Four sigmoids share one reciprocal.
__device__ __forceinline__ void lstm_unit(const ull acc[4], ull& c, ull& hout,
                                          ull CN2L2E, ull CONE, ull CTWO, ull CNONE)
{
    ull Ei = ex2_2(acc[0]);
    ull Ef = ex2_2(acc[1]);
    ull Eg = ex2_2(acc[2]);             // e^{-2g}
    ull Eo = ex2_2(acc[3]);
    ull Ai = add2(Ei, CONE), Bf = add2(Ef, CONE);
    ull Cg = add2(Eg, CONE), Do = add2(Eo, CONE);
    ull t1 = mul2(Ai, Bf), t2 = mul2(Cg, Do);
    ull r  = rcp2(mul2(t1, t2));
    ull q1 = mul2(r, t2), q2 = mul2(r, t1);
    ull si = mul2(q1, Bf);              // sigmoid(i)
    ull sf = mul2(q1, Ai);              // sigmoid(f)
    ull sg = mul2(q2, Do);              // sigmoid(2g)
    ull so = mul2(q2, Cg);              // sigmoid(o)
    ull tg = fma2(sg, CTWO, CNONE);     // tanh(g) = 2*sigmoid(2g) - 1
    c = fma2(sf, c, mul2(si, tg));      // c' = sig(f)*c + sig(i)*tanh(g)
    ull Ec = ex2_2(mul2(c, CN2L2E));    // e^{-2c}
    ull rc = rcp2(add2(Ec, CONE));      // sigmoid(2c)
    ull tc = fma2(rc, CTWO, CNONE);     // sigmoid(2c)*2-1 = tanh(c)
    hout = mul2(so, tc);
}

// Recurrent MAC for one pair: acc += W^T h, using register weights; 2 tree halves
__device__ __forceinline__ void rec_mac(ull acc[4], const ull Wr[8][4], const ull* hv)
{
    ulonglong2 h01 = *(const ulonglong2*)(hv + 0);
    ulonglong2 h23 = *(const ulonglong2*)(hv + 2);
    ulonglong2 h45 = *(const ulonglong2*)(hv + 4);
    ulonglong2 h67 = *(const ulonglong2*)(hv + 6);
    #pragma unroll
    for (int g = 0; g < 4; g++) {
        ull a = fma2(Wr[0][g], h01.x, acc[g]);
        a = fma2(Wr[1][g], h01.y, a);
        a = fma2(Wr[2][g], h23.x, a);
        a = fma2(Wr[3][g], h23.y, a);
        ull b = mul2(Wr[4][g], h45.x);
        b = fma2(Wr[5][g], h45.y, b);
        b = fma2(Wr[6][g], h67.x, b);
        b = fma2(Wr[7][g], h67.y, b);
        acc[g] = add2(a, b);
    }
}

// hw: this warp's h-exchange region, 2 buffers x 8 pairs x 8 units (128 ull)
template<int TSTEPS, int PH>
__device__ __forceinline__ void run_phase(ull* hw,
    const float* __restrict__ xbase, int P0, int q, int u,
    ull& hp0, ull& cp0, ull& hp1, ull& cp1,
    ull CN2L2E, ull CONE, ull CTWO, ull CNONE)
{
    // ---- phase-resident coefficients in registers (from global, once) ----
    ull Wr[8][4];
    #pragma unroll
    for (int k = 0; k < 8; k++) {
        const ulonglong2* ww = (const ulonglong2*)&gPack.W[PH][u][k][0];
        ulonglong2 q01 = __ldg(ww), q23 = __ldg(ww + 1);
        Wr[k][0] = q01.x; Wr[k][1] = q01.y; Wr[k][2] = q23.x; Wr[k][3] = q23.y;
    }
    ull A0[4], A1[4], Bz[4];
    {
        const ulonglong2* a0 = (const ulonglong2*)&gPack.A[PH][u][0][0];
        const ulonglong2* a1 = (const ulonglong2*)&gPack.A[PH][u][1][0];
        const ulonglong2* bz = (const ulonglong2*)&gPack.Bz[PH][u][0];
        ulonglong2 w01 = __ldg(a0), w23 = __ldg(a0 + 1);
        ulonglong2 v01 = __ldg(a1), v23 = __ldg(a1 + 1);
        ulonglong2 b01 = __ldg(bz), b23 = __ldg(bz + 1);
        A0[0] = w01.x; A0[1] = w01.y; A0[2] = w23.x; A0[3] = w23.y;
        A1[0] = v01.x; A1[1] = v01.y; A1[2] = v23.x; A1[3] = v23.y;
        Bz[0] = b01.x; Bz[1] = b01.y; Bz[2] = b23.x; Bz[3] = b23.y;
    }

    // x[t]: float4 index t*(NB/2) + P
    const float4* xp0 = (const float4*)xbase + (size_t)P0;
    const float4* xp1 = xp0 + 4;            // P1 = P0 + 4
    const size_t S4 = (size_t)NB / 2;       // float4 stride per timestep
    float4 xA = xp0[0], xB = xp1[0];        // prefetch t=0

    // publish initial h into buffer 0
    hw[(q << 3) + u] = hp0;
    hw[((q + 4) << 3) + u] = hp1;
    __syncwarp();

    #pragma unroll 1
    for (int t = 0; t < TSTEPS; t++) {
        ull acc0[4], acc1[4];
        {
            ull px0 = pk(xA.x, xA.z), px1 = pk(xA.y, xA.w);
            ull py0 = pk(xB.x, xB.z), py1 = pk(xB.y, xB.w);
            #pragma unroll
            for (int g = 0; g < 4; g++) {
                acc0[g] = fma2(A0[g], px0, Bz[g]); acc0[g] = fma2(A1[g], px1, acc0[g]);
                acc1[g] = fma2(A0[g], py0, Bz[g]); acc1[g] = fma2(A1[g], py1, acc1[g]);
            }
        }
        if (t + 1 < TSTEPS) {
            xA = xp0[(size_t)(t + 1) * S4];
            xB = xp1[(size_t)(t + 1) * S4];
        }

        const ull* hb = hw + ((t & 1) << 6);
        rec_mac(acc0, Wr, hb + (q << 3));
        rec_mac(acc1, Wr, hb + ((q + 4) << 3));

        lstm_unit(acc0, cp0, hp0, CN2L2E, CONE, CTWO, CNONE);
        lstm_unit(acc1, cp1, hp1, CN2L2E, CONE, CTWO, CNONE);

        if (t + 1 < TSTEPS) {
            ull* hn = hw + (((t + 1) & 1) << 6);
            hn[(q << 3) + u] = hp0;
            hn[((q + 4) << 3) + u] = hp1;
            __syncwarp();
        }
    }
}

__global__ void __launch_bounds__(128, 3)
enc_kernel(const float* __restrict__ obs, const float* __restrict__ pre,
           const float* __restrict__ h0, const float* __restrict__ c0,
           const float* __restrict__ c0p, float* __restrict__ out)
{
    __shared__ ull hbuf[4][128];             // per-warp: 2 bufs x 8 pairs x 8 units

    // warp = 8 pairs = 16 elements; lane = q*8 + u; lane handles pairs q and q+4
    const int lane = threadIdx.x & 31;
    const int warp = threadIdx.x >> 5;
    const int q = lane >> 3;                 // pair-slot (0..3)
    const int u = lane & 7;                  // hidden unit (0..7)
    const int gw = blockIdx.x * 4 + warp;    // global warp index
    const int P0 = gw * 8 + q;               // first pair
    const int P1 = P0 + 4;                   // second pair
    const int e0 = 2 * P0, e1 = 2 * P1;

    const ull CN2L2E = pk(-2.8853900817779268f, -2.8853900817779268f);
    const ull CONE   = pk(1.0f, 1.0f);
    const ull CTWO   = pk(2.0f, 2.0f);
    const ull CNONE  = pk(-1.0f, -1.0f);

    // initial state: [B,8] layout, stride 8
    ull hp0 = pk(h0[(size_t)e0 * 8 + u], h0[(size_t)(e0 + 1) * 8 + u]);
    ull cp0 = pk(c0[(size_t)e0 * 8 + u], c0[(size_t)(e0 + 1) * 8 + u]);
    ull hp1 = pk(h0[(size_t)e1 * 8 + u], h0[(size_t)(e1 + 1) * 8 + u]);
    ull cp1 = pk(c0[(size_t)e1 * 8 + u], c0[(size_t)(e1 + 1) * 8 + u]);

    run_phase<T_OBS, 0>(hbuf[warp], obs, P0, q, u, hp0, cp0, hp1, cp1,
                        CN2L2E, CONE, CTWO, CNONE);
    // c_out = transpose(h_obs): out[u*B + b]
    *(ull*)(out + (size_t)u * NB + e0) = hp0;
    *(ull*)(out + (size_t)u * NB + e1) = hp1;

    cp0 = pk(c0p[(size_t)e0 * 8 + u], c0p[(size_t)(e0 + 1) * 8 + u]);  // cell re-init
    cp1 = pk(c0p[(size_t)e1 * 8 + u], c0p[(size_t)(e1 + 1) * 8 + u]);
    run_phase<T_PRE, 1>(hbuf[warp], pre, P0, q, u, hp0, cp0, hp1, cp1,
                        CN2L2E, CONE, CTWO, CNONE);
    float* out2 = out + (size_t)NB * 8;
    *(ull*)(out2 + (size_t)u * NB + e0) = hp0;
    *(ull*)(out2 + (size_t)u * NB + e1) = hp1;
}

extern "C" void kernel_launch(void* const* d_in, const int* in_sizes, int n_in,
                              void* d_out, int out_size)
{
    const float* obs   = (const float*)d_in[0];
    const float* pre   = (const float*)d_in[1];
    const float* h0    = (const float*)d_in[2];
    const float* c0    = (const float*)d_in[3];
    const float* c0p   = (const float*)d_in[4];
    const float* W_in  = (const float*)d_in[5];
    const float* b_in  = (const float*)d_in[6];
    const float* Wih_o = (const float*)d_in[7];
    const float* Whh_o = (const float*)d_in[8];
    const float* bih_o = (const float*)d_in[9];
    const float* bhh_o = (const float*)d_in[10];
    const float* Wih_p = (const float*)d_in[11];
    const float* Whh_p = (const float*)d_in[12];
    const float* bih_p = (const float*)d_in[13];
    const float* bhh_p = (const float*)d_in[14];

    prep_kernel<<<1, 64>>>(W_in, b_in, Wih_o, Whh_o, bih_o, bhh_o,
                           Wih_p, Whh_p, bih_p, bhh_p);
    // 1 warp = 16 elems, 4 warps/block -> 64 elems/block
    enc_kernel<<<NB / 64, 128>>>(obs, pre, h0, c0, c0p, (float*)d_out);
}

// round 9
// speedup vs baseline: 6.8118x; 1.1609x over previous
#include <cuda_runtime.h>

#define NB 524288
#define T_OBS 8
#define T_PRE 12
#define HH 8
#define EE 16

typedef unsigned long long ull;

// Duplicated (w,w) packed weights.
// Gates i,f,o pre-scaled by 0.5 (sigmoid(x)=0.5*tanh(x/2)+0.5); gate g unscaled.
struct __align__(16) Wpack {
    float2 W[2][8][8][4];   // [phase][u][k][gate]
    float2 A[2][8][2][4];   // [phase][u][m][gate]   (A = W_ih @ W_in, folded)
    float2 Bz[2][8][4];     // [phase][u][gate]      (b_ih + b_hh + W_ih@b_in, folded)
};
__device__ Wpack gPack;

// ---------------- prep: fold embedding into gate weights, scale, duplicate ----------------
__global__ void prep_kernel(
    const float* __restrict__ W_in, const float* __restrict__ b_in,
    const float* __restrict__ Wih_o, const float* __restrict__ Whh_o,
    const float* __restrict__ bih_o, const float* __restrict__ bhh_o,
    const float* __restrict__ Wih_p, const float* __restrict__ Whh_p,
    const float* __restrict__ bih_p, const float* __restrict__ bhh_p)
{
    int t = threadIdx.x;
    if (t >= 64) return;
    int ph = t >> 5, r = t & 31;
    const float* Wih = ph ? Wih_p : Wih_o;
    const float* Whh = ph ? Whh_p : Whh_o;
    const float* bih = ph ? bih_p : bih_o;
    const float* bhh = ph ? bhh_p : bhh_o;
    int g = r >> 3, j = r & 7;                       // rows: i(0-7) f(8-15) g(16-23) o(24-31)
    float sc = (g == 2) ? 1.0f : 0.5f;               // sigmoid via tanh(x/2); g: tanh direct
    float a0 = 0.f, a1 = 0.f, bb = bih[r] + bhh[r];
    for (int e = 0; e < EE; e++) {
        float w = Wih[r * EE + e];
        a0 += w * W_in[e * 2 + 0];
        a1 += w * W_in[e * 2 + 1];
        bb += w * b_in[e];
    }
    a0 *= sc; a1 *= sc; bb *= sc;
    gPack.A[ph][j][0][g] = make_float2(a0, a0);
    gPack.A[ph][j][1][g] = make_float2(a1, a1);
    gPack.Bz[ph][j][g]   = make_float2(bb, bb);
    for (int k = 0; k < HH; k++) {
        float w = Whh[r * HH + k] * sc;
        gPack.W[ph][j][k][g] = make_float2(w, w);
    }
}

// ---------------- packed f32x2 helpers ----------------
__device__ __forceinline__ ull fma2(ull a, ull b, ull c) {
    ull d; asm("fma.rn.f32x2 %0, %1, %2, %3;" : "=l"(d) : "l"(a), "l"(b), "l"(c)); return d;
}
__device__ __forceinline__ ull mul2(ull a, ull b) {
    ull d; asm("mul.rn.f32x2 %0, %1, %2;" : "=l"(d) : "l"(a), "l"(b)); return d;
}
__device__ __forceinline__ ull add2(ull a, ull b) {
    ull d; asm("add.rn.f32x2 %0, %1, %2;" : "=l"(d) : "l"(a), "l"(b)); return d;
}
__device__ __forceinline__ ull pk(float lo, float hi) {
    ull d; asm("mov.b64 %0, {%1, %2};" : "=l"(d) : "f"(lo), "f"(hi)); return d;
}
__device__ __forceinline__ void unpk(ull v, float& lo, float& hi) {
    asm("mov.b64 {%0, %1}, %2;" : "=f"(lo), "=f"(hi) : "l"(v));
}
__device__ __forceinline__ float tanhap(float x) {
    float y; asm("tanh.approx.f32 %0, %1;" : "=f"(y) : "f"(x)); return y;
}

// LSTM epilogue, scalar per lane. acc = [i/2, f/2, g, o/2] preactivations (packed).
// c kept as two scalars; h repacked at the end for the smem exchange.
__device__ __forceinline__ void lstm_unit(const ull acc[4], float& cl, float& ch, ull& hout)
{
    float il, ih, fl, fh, gl, gh, ol, oh;
    unpk(acc[0], il, ih);
    unpk(acc[1], fl, fh);
    unpk(acc[2], gl, gh);
    unpk(acc[3], ol, oh);
    float til = tanhap(il), tih = tanhap(ih);
    float tfl = tanhap(fl), tfh = tanhap(fh);
    float tgl = tanhap(gl), tgh = tanhap(gh);
    float tol = tanhap(ol), toh = tanhap(oh);
    float sil = fmaf(til, 0.5f, 0.5f), sih = fmaf(tih, 0.5f, 0.5f);
    float sfl = fmaf(tfl, 0.5f, 0.5f), sfh = fmaf(tfh, 0.5f, 0.5f);
    float sol = fmaf(tol, 0.5f, 0.5f), soh = fmaf(toh, 0.5f, 0.5f);
    cl = fmaf(sfl, cl, sil * tgl);
    ch = fmaf(sfh, ch, sih * tgh);
    float tcl = tanhap(cl), tch = tanhap(ch);
    hout = pk(sol * tcl, soh * tch);
}

// Recurrent MAC for one pair: acc += W^T h, register weights; 2 tree halves
__device__ __forceinline__ void rec_mac(ull acc[4], const ull Wr[8][4], const ull* hv)
{
    ulonglong2 h01 = *(const ulonglong2*)(hv + 0);
    ulonglong2 h23 = *(const ulonglong2*)(hv + 2);
    ulonglong2 h45 = *(const ulonglong2*)(hv + 4);
    ulonglong2 h67 = *(const ulonglong2*)(hv + 6);
    #pragma unroll
    for (int g = 0; g < 4; g++) {
        ull a = fma2(Wr[0][g], h01.x, acc[g]);
        a = fma2(Wr[1][g], h01.y, a);
        a = fma2(Wr[2][g], h23.x, a);
        a = fma2(Wr[3][g], h23.y, a);
        ull b = mul2(Wr[4][g], h45.x);
        b = fma2(Wr[5][g], h45.y, b);
        b = fma2(Wr[6][g], h67.x, b);
        b = fma2(Wr[7][g], h67.y, b);
        acc[g] = add2(a, b);
    }
}

// hw: this warp's h-exchange region, 2 buffers x 8 pairs x 8 units (128 ull)
template<int TSTEPS, int PH>
__device__ __forceinline__ void run_phase(ull* hw,
    const float* __restrict__ xbase, int P0, int q, int u,
    ull& hp0, ull& hp1,
    float& c0l, float& c0h, float& c1l, float& c1h)
{
    // ---- phase-resident coefficients in registers (from global, once) ----
    ull Wr[8][4];
    #pragma unroll
    for (int k = 0; k < 8; k++) {
        const ulonglong2* ww = (const ulonglong2*)&gPack.W[PH][u][k][0];
        ulonglong2 q01 = __ldg(ww), q23 = __ldg(ww + 1);
        Wr[k][0] = q01.x; Wr[k][1] = q01.y; Wr[k][2] = q23.x; Wr[k][3] = q23.y;
    }
    ull A0[4], A1[4], Bz[4];
    {
        const ulonglong2* a0 = (const ulonglong2*)&gPack.A[PH][u][0][0];
        const ulonglong2* a1 = (const ulonglong2*)&gPack.A[PH][u][1][0];
        const ulonglong2* bz = (const ulonglong2*)&gPack.Bz[PH][u][0];
        ulonglong2 w01 = __ldg(a0), w23 = __ldg(a0 + 1);
        ulonglong2 v01 = __ldg(a1), v23 = __ldg(a1 + 1);
        ulonglong2 b01 = __ldg(bz), b23 = __ldg(bz + 1);
        A0[0] = w01.x; A0[1] = w01.y; A0[2] = w23.x; A0[3] = w23.y;
        A1[0] = v01.x; A1[1] = v01.y; A1[2] = v23.x; A1[3] = v23.y;
        Bz[0] = b01.x; Bz[1] = b01.y; Bz[2] = b23.x; Bz[3] = b23.y;
    }

    // x[t]: float4 index t*(NB/2) + P
    const float4* xp0 = (const float4*)xbase + (size_t)P0;
    const float4* xp1 = xp0 + 4;            // P1 = P0 + 4
    const size_t S4 = (size_t)NB / 2;       // float4 stride per timestep
    float4 xA = xp0[0], xB = xp1[0];        // prefetch t=0

    // publish initial h into buffer 0
    hw[(q << 3) + u] = hp0;
    hw[((q + 4) << 3) + u] = hp1;
    __syncwarp();

    #pragma unroll 1
    for (int t = 0; t < TSTEPS; t++) {
        ull acc0[4], acc1[4];
        {
            ull px0 = pk(xA.x, xA.z), px1 = pk(xA.y, xA.w);
            ull py0 = pk(xB.x, xB.z), py1 = pk(xB.y, xB.w);
            #pragma unroll
            for (int g = 0; g < 4; g++) {
                acc0[g] = fma2(A0[g], px0, Bz[g]); acc0[g] = fma2(A1[g], px1, acc0[g]);
                acc1[g] = fma2(A0[g], py0, Bz[g]); acc1[g] = fma2(A1[g], py1, acc1[g]);
            }
        }
        if (t + 1 < TSTEPS) {
            xA = xp0[(size_t)(t + 1) * S4];
            xB = xp1[(size_t)(t + 1) * S4];
        }

        const ull* hb = hw + ((t & 1) << 6);
        rec_mac(acc0, Wr, hb + (q << 3));
        rec_mac(acc1, Wr, hb + ((q + 4) << 3));

        lstm_unit(acc0, c0l, c0h, hp0);
        lstm_unit(acc1, c1l, c1h, hp1);

        if (t + 1 < TSTEPS) {
            ull* hn = hw + (((t + 1) & 1) << 6);
            hn[(q << 3) + u] = hp0;
            hn[((q + 4) << 3) + u] = hp1;
            __syncwarp();
        }
    }
}

__global__ void __launch_bounds__(128, 3)
enc_kernel(const float* __restrict__ obs, const float* __restrict__ pre,
           const float* __restrict__ h0, const float* __restrict__ c0,
           const float* __restrict__ c0p, float* __restrict__ out)
{
    __shared__ ull hbuf[4][128];             // per-warp: 2 bufs x 8 pairs x 8 units

    // warp = 8 pairs = 16 elements; lane = q*8 + u; lane handles pairs q and q+4
    const int lane = threadIdx.x & 31;
    const int warp = threadIdx.x >> 5;
    const int q = lane >> 3;                 // pair-slot (0..3)
    const int u = lane & 7;                  // hidden unit (0..7)
    const int gw = blockIdx.x * 4 + warp;    // global warp index
    const int P0 = gw * 8 + q;               // first pair
    const int P1 = P0 + 4;                   // second pair
    const int e0 = 2 * P0, e1 = 2 * P1;

    // initial state: [B,8] layout, stride 8
    ull hp0 = pk(h0[(size_t)e0 * 8 + u], h0[(size_t)(e0 + 1) * 8 + u]);
    ull hp1 = pk(h0[(size_t)e1 * 8 + u], h0[(size_t)(e1 + 1) * 8 + u]);
    float c0l = c0[(size_t)e0 * 8 + u], c0h = c0[(size_t)(e0 + 1) * 8 + u];
    float c1l = c0[(size_t)e1 * 8 + u], c1h = c0[(size_t)(e1 + 1) * 8 + u];

    run_phase<T_OBS, 0>(hbuf[warp], obs, P0, q, u, hp0, hp1, c0l, c0h, c1l, c1h);
    // c_out = transpose(h_obs): out[u*B + b]
    *(ull*)(out + (size_t)u * NB + e0) = hp0;
    *(ull*)(out + (size_t)u * NB + e1) = hp1;

    c0l = c0p[(size_t)e0 * 8 + u]; c0h = c0p[(size_t)(e0 + 1) * 8 + u];  // cell re-init
    c1l = c0p[(size_t)e1 * 8 + u]; c1h = c0p[(size_t)(e1 + 1) * 8 + u];
    run_phase<T_PRE, 1>(hbuf[warp], pre, P0, q, u, hp0, hp1, c0l, c0h, c1l, c1h);
    float* out2 = out + (size_t)NB * 8;
    *(ull*)(out2 + (size_t)u * NB + e0) = hp0;
    *(ull*)(out2 + (size_t)u * NB + e1) = hp1;
}

extern "C" void kernel_launch(void* const* d_in, const int* in_sizes, int n_in,
                              void* d_out, int out_size)
{
    const float* obs   = (const float*)d_in[0];
    const float* pre   = (const float*)d_in[1];
    const float* h0    = (const float*)d_in[2];
    const float* c0    = (const float*)d_in[3];
    const float* c0p   = (const float*)d_in[4];
    const float* W_in  = (const float*)d_in[5];
    const float* b_in  = (const float*)d_in[6];
    const float* Wih_o = (const float*)d_in[7];
    const float* Whh_o = (const float*)d_in[8];
    const float* bih_o = (const float*)d_in[9];
    const float* bhh_o = (const float*)d_in[10];
    const float* Wih_p = (const float*)d_in[11];
    const float* Whh_p = (const float*)d_in[12];
    const float* bih_p = (const float*)d_in[13];
    const float* bhh_p = (const float*)d_in[14];

    prep_kernel<<<1, 64>>>(W_in, b_in, Wih_o, Whh_o, bih_o, bhh_o,
                           Wih_p, Whh_p, bih_p, bhh_p);
    // 1 warp = 16 elems, 4 warps/block -> 64 elems/block
    enc_kernel<<<NB / 64, 128>>>(obs, pre, h0, c0, c0p, (float*)d_out);
}

// round 10
// speedup vs baseline: 7.5470x; 1.1079x over previous
#include <cuda_runtime.h>

#define NB 524288
#define T_OBS 8
#define T_PRE 12
#define HH 8
#define EE 16

typedef unsigned long long ull;

// Duplicated (w,w) packed weights.
// Gates i,f,o pre-scaled by 0.5 (sigmoid(x)=0.5*tanh(x/2)+0.5); gate g unscaled.
struct __align__(16) Wpack {
    float2 W[2][8][8][4];   // [phase][u][k][gate]
    float2 A[2][8][2][4];   // [phase][u][m][gate]   (A = W_ih @ W_in, folded)
    float2 Bz[2][8][4];     // [phase][u][gate]      (b_ih + b_hh + W_ih@b_in, folded)
};
__device__ Wpack gPack;

// ---------------- prep: fold embedding into gate weights, scale, duplicate ----------------
__global__ void prep_kernel(
    const float* __restrict__ W_in, const float* __restrict__ b_in,
    const float* __restrict__ Wih_o, const float* __restrict__ Whh_o,
    const float* __restrict__ bih_o, const float* __restrict__ bhh_o,
    const float* __restrict__ Wih_p, const float* __restrict__ Whh_p,
    const float* __restrict__ bih_p, const float* __restrict__ bhh_p)
{
    int t = threadIdx.x;
    if (t >= 64) return;
    int ph = t >> 5, r = t & 31;
    const float* Wih = ph ? Wih_p : Wih_o;
    const float* Whh = ph ? Whh_p : Whh_o;
    const float* bih = ph ? bih_p : bih_o;
    const float* bhh = ph ? bhh_p : bhh_o;
    int g = r >> 3, j = r & 7;                       // rows: i(0-7) f(8-15) g(16-23) o(24-31)
    float sc = (g == 2) ? 1.0f : 0.5f;               // sigmoid via tanh(x/2); g: tanh direct
    float a0 = 0.f, a1 = 0.f, bb = bih[r] + bhh[r];
    for (int e = 0; e < EE; e++) {
        float w = Wih[r * EE + e];
        a0 += w * W_in[e * 2 + 0];
        a1 += w * W_in[e * 2 + 1];
        bb += w * b_in[e];
    }
    a0 *= sc; a1 *= sc; bb *= sc;
    gPack.A[ph][j][0][g] = make_float2(a0, a0);
    gPack.A[ph][j][1][g] = make_float2(a1, a1);
    gPack.Bz[ph][j][g]   = make_float2(bb, bb);
    for (int k = 0; k < HH; k++) {
        float w = Whh[r * HH + k] * sc;
        gPack.W[ph][j][k][g] = make_float2(w, w);
    }
}

// ---------------- packed f32x2 helpers ----------------
__device__ __forceinline__ ull fma2(ull a, ull b, ull c) {
    ull d; asm("fma.rn.f32x2 %0, %1, %2, %3;" : "=l"(d) : "l"(a), "l"(b), "l"(c)); return d;
}
__device__ __forceinline__ ull mul2(ull a, ull b) {
    ull d; asm("mul.rn.f32x2 %0, %1, %2;" : "=l"(d) : "l"(a), "l"(b)); return d;
}
__device__ __forceinline__ ull add2(ull a, ull b) {
    ull d; asm("add.rn.f32x2 %0, %1, %2;" : "=l"(d) : "l"(a), "l"(b)); return d;
}
__device__ __forceinline__ ull pk(float lo, float hi) {
    ull d; asm("mov.b64 %0, {%1, %2};" : "=l"(d) : "f"(lo), "f"(hi)); return d;
}
__device__ __forceinline__ void unpk(ull v, float& lo, float& hi) {
    asm("mov.b64 {%0, %1}, %2;" : "=f"(lo), "=f"(hi) : "l"(v));
}
__device__ __forceinline__ float tanhap(float x) {
    float y; asm("tanh.approx.f32 %0, %1;" : "=f"(y) : "f"(x)); return y;
}
__device__ __forceinline__ void cp16(unsigned dst, const void* src) {
    asm volatile("cp.async.cg.shared.global [%0], [%1], 16;" :: "r"(dst), "l"(src) : "memory");
}
__device__ __forceinline__ void cp_commit() {
    asm volatile("cp.async.commit_group;" ::: "memory");
}
__device__ __forceinline__ void cp_wait1() {
    asm volatile("cp.async.wait_group 1;" ::: "memory");
}

// LSTM epilogue, scalar per lane. acc = [i/2, f/2, g, o/2] preactivations (packed).
__device__ __forceinline__ void lstm_unit(const ull acc[4], float& cl, float& ch, ull& hout)
{
    float il, ih, fl, fh, gl, gh, ol, oh;
    unpk(acc[0], il, ih);
    unpk(acc[1], fl, fh);
    unpk(acc[2], gl, gh);
    unpk(acc[3], ol, oh);
    float til = tanhap(il), tih = tanhap(ih);
    float tfl = tanhap(fl), tfh = tanhap(fh);
    float tgl = tanhap(gl), tgh = tanhap(gh);
    float tol = tanhap(ol), toh = tanhap(oh);
    float sil = fmaf(til, 0.5f, 0.5f), sih = fmaf(tih, 0.5f, 0.5f);
    float sfl = fmaf(tfl, 0.5f, 0.5f), sfh = fmaf(tfh, 0.5f, 0.5f);
    float sol = fmaf(tol, 0.5f, 0.5f), soh = fmaf(toh, 0.5f, 0.5f);
    cl = fmaf(sfl, cl, sil * tgl);
    ch = fmaf(sfh, ch, sih * tgh);
    float tcl = tanhap(cl), tch = tanhap(ch);
    hout = pk(sol * tcl, soh * tch);
}

// Recurrent MAC for one pair: acc += W^T h, register weights; 2 tree halves
__device__ __forceinline__ void rec_mac(ull acc[4], const ull Wr[8][4], const ull* hv)
{
    ulonglong2 h01 = *(const ulonglong2*)(hv + 0);
    ulonglong2 h23 = *(const ulonglong2*)(hv + 2);
    ulonglong2 h45 = *(const ulonglong2*)(hv + 4);
    ulonglong2 h67 = *(const ulonglong2*)(hv + 6);
    #pragma unroll
    for (int g = 0; g < 4; g++) {
        ull a = fma2(Wr[0][g], h01.x, acc[g]);
        a = fma2(Wr[1][g], h01.y, a);
        a = fma2(Wr[2][g], h23.x, a);
        a = fma2(Wr[3][g], h23.y, a);
        ull b = mul2(Wr[4][g], h45.x);
        b = fma2(Wr[5][g], h45.y, b);
        b = fma2(Wr[6][g], h67.x, b);
        b = fma2(Wr[7][g], h67.y, b);
        acc[g] = add2(a, b);
    }
}

// hw: this warp's h-exchange region (2 bufs x 8 pairs x 8 units = 128 ull)
// xs: this warp's x-staging region (4 slots x 8 pairs x float4)
template<int TSTEPS, int PH>
__device__ __forceinline__ void run_phase(ull* hw, float4* xs,
    const float* __restrict__ xbase, int P0, int q, int u,
    ull& hp0, ull& hp1,
    float& c0l, float& c0h, float& c1l, float& c1h)
{
    // ---- phase-resident coefficients in registers (from global, once) ----
    ull Wr[8][4];
    #pragma unroll
    for (int k = 0; k < 8; k++) {
        const ulonglong2* ww = (const ulonglong2*)&gPack.W[PH][u][k][0];
        ulonglong2 q01 = __ldg(ww), q23 = __ldg(ww + 1);
        Wr[k][0] = q01.x; Wr[k][1] = q01.y; Wr[k][2] = q23.x; Wr[k][3] = q23.y;
    }
    ull A0[4], A1[4], Bz[4];
    {
        const ulonglong2* a0 = (const ulonglong2*)&gPack.A[PH][u][0][0];
        const ulonglong2* a1 = (const ulonglong2*)&gPack.A[PH][u][1][0];
        const ulonglong2* bz = (const ulonglong2*)&gPack.Bz[PH][u][0];
        ulonglong2 w01 = __ldg(a0), w23 = __ldg(a0 + 1);
        ulonglong2 v01 = __ldg(a1), v23 = __ldg(a1 + 1);
        ulonglong2 b01 = __ldg(bz), b23 = __ldg(bz + 1);
        A0[0] = w01.x; A0[1] = w01.y; A0[2] = w23.x; A0[3] = w23.y;
        A1[0] = v01.x; A1[1] = v01.y; A1[2] = v23.x; A1[3] = v23.y;
        Bz[0] = b01.x; Bz[1] = b01.y; Bz[2] = b23.x; Bz[3] = b23.y;
    }

    const float4* gx = (const float4*)xbase;   // x[t] for pair P: gx[t*S4 + P]
    const size_t S4 = (size_t)NB / 2;
    const unsigned xs_u32 = (unsigned)__cvta_generic_to_shared(xs);

    __syncwarp();   // prior readers of xs (previous phase) are done

    // prefill slots 0,1 (t=0,1); only lane u==0 of each pair group copies
    if (u == 0) {
        cp16(xs_u32 + (unsigned)((0 * 8 + q) * 16),     gx + P0);
        cp16(xs_u32 + (unsigned)((0 * 8 + q + 4) * 16), gx + P0 + 4);
    }
    cp_commit();
    if (u == 0) {
        cp16(xs_u32 + (unsigned)((1 * 8 + q) * 16),     gx + S4 + P0);
        cp16(xs_u32 + (unsigned)((1 * 8 + q + 4) * 16), gx + S4 + P0 + 4);
    }
    cp_commit();

    // publish initial h into buffer 0 (ordered by the syncwarp at loop top)
    hw[(q << 3) + u] = hp0;
    hw[((q + 4) << 3) + u] = hp1;

    #pragma unroll 4
    for (int t = 0; t < TSTEPS; t++) {
        cp_wait1();          // lane u==0: slot t&3 landed; others: no-op
        __syncwarp();        // make lane0's cp.async data + last step's STS visible

        float4 xA = xs[(t & 3) * 8 + q];
        float4 xB = xs[(t & 3) * 8 + q + 4];

        ull acc0[4], acc1[4];
        {
            ull px0 = pk(xA.x, xA.z), px1 = pk(xA.y, xA.w);
            ull py0 = pk(xB.x, xB.z), py1 = pk(xB.y, xB.w);
            #pragma unroll
            for (int g = 0; g < 4; g++) {
                acc0[g] = fma2(A0[g], px0, Bz[g]); acc0[g] = fma2(A1[g], px1, acc0[g]);
                acc1[g] = fma2(A0[g], py0, Bz[g]); acc1[g] = fma2(A1[g], py1, acc1[g]);
            }
        }

        // issue prefetch for t+2 (distance 2)
        if (t + 2 < TSTEPS) {
            if (u == 0) {
                const float4* src = gx + (size_t)(t + 2) * S4;
                cp16(xs_u32 + (unsigned)((((t + 2) & 3) * 8 + q) * 16),     src + P0);
                cp16(xs_u32 + (unsigned)((((t + 2) & 3) * 8 + q + 4) * 16), src + P0 + 4);
            }
        }
        cp_commit();         // always commit (possibly empty) to keep group counting uniform

        const ull* hb = hw + ((t & 1) << 6);
        rec_mac(acc0, Wr, hb + (q << 3));
        rec_mac(acc1, Wr, hb + ((q + 4) << 3));

        lstm_unit(acc0, c0l, c0h, hp0);
        lstm_unit(acc1, c1l, c1h, hp1);

        if (t + 1 < TSTEPS) {
            ull* hn = hw + (((t + 1) & 1) << 6);
            hn[(q << 3) + u] = hp0;
            hn[((q + 4) << 3) + u] = hp1;
            // visibility handled by the syncwarp at the top of the next step
        }
    }
}

__global__ void __launch_bounds__(128, 3)
enc_kernel(const float* __restrict__ obs, const float* __restrict__ pre,
           const float* __restrict__ h0, const float* __restrict__ c0,
           const float* __restrict__ c0p, float* __restrict__ out)
{
    __shared__ ull hbuf[4][128];             // per-warp: 2 bufs x 8 pairs x 8 units
    __shared__ float4 xbuf[4][4][8];         // per-warp: 4 slots x 8 pairs

    // warp = 8 pairs = 16 elements; lane = q*8 + u; lane handles pairs q and q+4
    const int lane = threadIdx.x & 31;
    const int warp = threadIdx.x >> 5;
    const int q = lane >> 3;                 // pair-slot (0..3)
    const int u = lane & 7;                  // hidden unit (0..7)
    const int gw = blockIdx.x * 4 + warp;    // global warp index
    const int P0 = gw * 8 + q;               // first pair
    const int P1 = P0 + 4;                   // second pair
    const int e0 = 2 * P0, e1 = 2 * P1;

    // initial state: [B,8] layout, stride 8
    ull hp0 = pk(h0[(size_t)e0 * 8 + u], h0[(size_t)(e0 + 1) * 8 + u]);
    ull hp1 = pk(h0[(size_t)e1 * 8 + u], h0[(size_t)(e1 + 1) * 8 + u]);
    float c0l = c0[(size_t)e0 * 8 + u], c0h = c0[(size_t)(e0 + 1) * 8 + u];
    float c1l = c0[(size_t)e1 * 8 + u], c1h = c0[(size_t)(e1 + 1) * 8 + u];

    run_phase<T_OBS, 0>(hbuf[warp], &xbuf[warp][0][0], obs, P0, q, u,
                        hp0, hp1, c0l, c0h, c1l, c1h);
    // c_out = transpose(h_obs): out[u*B + b]
    *(ull*)(out + (size_t)u * NB + e0) = hp0;
    *(ull*)(out + (size_t)u * NB + e1) = hp1;

    c0l = c0p[(size_t)e0 * 8 + u]; c0h = c0p[(size_t)(e0 + 1) * 8 + u];  // cell re-init
    c1l = c0p[(size_t)e1 * 8 + u]; c1h = c0p[(size_t)(e1 + 1) * 8 + u];
    run_phase<T_PRE, 1>(hbuf[warp], &xbuf[warp][0][0], pre, P0, q, u,
                        hp0, hp1, c0l, c0h, c1l, c1h);
    float* out2 = out + (size_t)NB * 8;
    *(ull*)(out2 + (size_t)u * NB + e0) = hp0;
    *(ull*)(out2 + (size_t)u * NB + e1) = hp1;
}

extern "C" void kernel_launch(void* const* d_in, const int* in_sizes, int n_in,
                              void* d_out, int out_size)
{
    const float* obs   = (const float*)d_in[0];
    const float* pre   = (const float*)d_in[1];
    const float* h0    = (const float*)d_in[2];
    const float* c0    = (const float*)d_in[3];
    const float* c0p   = (const float*)d_in[4];
    const float* W_in  = (const float*)d_in[5];
    const float* b_in  = (const float*)d_in[6];
    const float* Wih_o = (const float*)d_in[7];
    const float* Whh_o = (const float*)d_in[8];
    const float* bih_o = (const float*)d_in[9];
    const float* bhh_o = (const float*)d_in[10];
    const float* Wih_p = (const float*)d_in[11];
    const float* Whh_p = (const float*)d_in[12];
    const float* bih_p = (const float*)d_in[13];
    const float* bhh_p = (const float*)d_in[14];

    prep_kernel<<<1, 64>>>(W_in, b_in, Wih_o, Whh_o, bih_o, bhh_o,
                           Wih_p, Whh_p, bih_p, bhh_p);
    // 1 warp = 16 elems, 4 warps/block -> 64 elems/block
    enc_kernel<<<NB / 64, 128>>>(obs, pre, h0, c0, c0p, (float*)d_out);
}